// round 14
// baseline (speedup 1.0000x reference)
#include <cuda_runtime.h>
#include <stdint.h>

#define Bc    64
#define CIN   256
#define COUT  256
#define HW    28
#define NPIX  (HW*HW)            // 784
#define NW    (COUT*CIN*9)       // 589824
#define KK    8
#define PDIM  30
#define PPIX  (PDIM*PDIM)        // 900

// ---------------- device scratch ----------------
__device__ __align__(16) uint32_t g_w[COUT * 9 * 8];          // [o][t][cw] sign bits
__device__ int                    g_corr[COUT * 9];           // 256 - 2*popc(w[o][t])
__device__ __align__(16) uint32_t g_pabits[(size_t)Bc * PPIX * 8]; // padded bit image

__device__ __forceinline__ uint32_t xor3(uint32_t a, uint32_t b, uint32_t c) {
    uint32_t r;
    asm("lop3.b32 %0, %1, %2, %3, 0x96;" : "=r"(r) : "r"(a), "r"(b), "r"(c));
    return r;
}
__device__ __forceinline__ uint32_t maj3(uint32_t a, uint32_t b, uint32_t c) {
    uint32_t r;
    asm("lop3.b32 %0, %1, %2, %3, 0xE8;" : "=r"(r) : "r"(a), "r"(b), "r"(c));
    return r;
}

// ---------------------------------------------------------------------------
// Kernel 1: fused prep. Blocks [0,256): weights; [256,481): activations.
// ---------------------------------------------------------------------------
__global__ void prep_kernel(const float* __restrict__ M, const float* __restrict__ Z,
                            const float* __restrict__ rv, const float* __restrict__ x)
{
    __shared__ float swv[2304];
    __shared__ int   sP[9];

    if (blockIdx.x < COUT) {
        const int o    = blockIdx.x;
        const int c    = threadIdx.x;
        const int lane = c & 31;
        const int cw   = c >> 5;

        if (c < 9) sP[c] = 0;

        float rvl[KK];
#pragma unroll
        for (int k = 0; k < KK; k++) rvl[k] = __ldg(rv + k);

        float wv9[9];
        {
            const float* Mp = M + (size_t)o * 2304;
#pragma unroll
            for (int i = 0; i < 9; i++) wv9[i] = Mp[i * 256 + c];
#pragma unroll
            for (int k = 0; k < KK; k++) {
                const float* zp = Z + (size_t)k * NW + (size_t)o * 2304;
#pragma unroll
                for (int i = 0; i < 9; i++) wv9[i] += rvl[k] * zp[i * 256 + c];
            }
        }
#pragma unroll
        for (int i = 0; i < 9; i++) swv[i * 256 + c] = wv9[i];
        __syncthreads();

#pragma unroll
        for (int j = 0; j < 9; j++) {
            unsigned bit  = __float_as_uint(swv[c * 9 + j]) >> 31;
            unsigned mask = __ballot_sync(0xffffffffu, bit);
            if (lane == 0) {
                g_w[(o * 9 + j) * 8 + cw] = mask;
                atomicAdd(&sP[j], __popc(mask));
            }
        }
        __syncthreads();
        if (c < 9) g_corr[o * 9 + c] = 256 - 2 * sP[c];
        return;
    }

    const int gid = (blockIdx.x - COUT) * 256 + threadIdx.x;
    if (gid >= Bc * PPIX) return;
    const int b  = gid / PPIX;
    const int pp = gid - b * PPIX;
    const int py = pp / PDIM;
    const int px = pp - py * PDIM;

    uint4* dst = (uint4*)(g_pabits + ((size_t)b * PPIX + pp) * 8);

    if (py == 0 || py == PDIM - 1 || px == 0 || px == PDIM - 1) {
        uint4 z = make_uint4(0, 0, 0, 0);
        dst[0] = z; dst[1] = z;
        return;
    }
    const float* xp = x + (size_t)b * CIN * NPIX + (py - 1) * HW + (px - 1);
    uint32_t w[8];
#pragma unroll
    for (int cw = 0; cw < 8; cw++) {
        uint32_t m = 0;
#pragma unroll
        for (int j = 0; j < 32; j++) {
            uint32_t s = __float_as_uint(xp[(size_t)(cw * 32 + j) * NPIX]) >> 31;
            m |= s << j;
        }
        w[cw] = m;
    }
    dst[0] = make_uint4(w[0], w[1], w[2], w[3]);
    dst[1] = make_uint4(w[4], w[5], w[6], w[7]);
}

// ---------------------------------------------------------------------------
// Kernel 2: CSA XNOR conv. 256 thr (8 warps = 8 og), 7-row bands, kh-outer
// weight streaming (24 live weight words), two 14-col half-passes per row.
// 3 CTAs/SM -> 24 warps. grid <<<256, 256, 38336>>>
// ---------------------------------------------------------------------------
#define SM_ABITS 0                      // 9 rows x 30 px x 32B = 8640
#define SM_STAGE 8640                   // 8 og x 32 x 29 floats = 29696
#define SM_TOTAL (8640 + 29696)

__global__ void __launch_bounds__(256, 3)
conv_pop_kernel(const float* __restrict__ alpha, float* __restrict__ out)
{
    extern __shared__ __align__(16) uint8_t smem[];

    const int tid  = threadIdx.x;
    const int og   = tid >> 5;
    const int lane = tid & 31;

    const int b    = blockIdx.x >> 2;
    const int band = blockIdx.x & 3;
    const int r0   = band * 7;

    // cooperative load: padded rows r0..r0+8 (540 uint4, contiguous)
    {
        const uint4* src = (const uint4*)(g_pabits + ((size_t)b * PPIX + r0 * PDIM) * 8);
        uint4* d4 = (uint4*)(smem + SM_ABITS);
        d4[tid] = src[tid];
        d4[tid + 256] = src[tid + 256];
        if (tid < 28) d4[tid + 512] = src[tid + 512];
    }

    const int o = og * 32 + lane;
    int corr[9];
#pragma unroll
    for (int t = 0; t < 9; t++) corr[t] = __ldg(g_corr + o * 9 + t);
    const float av = __ldg(alpha + o);
    const uint4* wbase = (const uint4*)(g_w + o * 72);

    __syncthreads();

    const uint32_t* ab = (const uint32_t*)(smem + SM_ABITS);
    float* stage = (float*)(smem + SM_STAGE) + og * (32 * 29);

#pragma unroll 1
    for (int ry = 0; ry < 7; ry++) {
        const int y = r0 + ry;

        const int rowc = (y == 0)  ? (corr[0] + corr[1] + corr[2])
                       : (y == 27) ? (corr[6] + corr[7] + corr[8]) : 0;

#pragma unroll 1
        for (int half = 0; half < 2; half++) {
            const int xs = half * 14;

            int acc[14];
#pragma unroll
            for (int i = 0; i < 14; i++) acc[i] = 0;

#pragma unroll 1
            for (int kh = 0; kh < 3; kh++) {
                const uint4* wp = wbase + kh * 6;
                uint32_t w[3][8];
#pragma unroll
                for (int kw = 0; kw < 3; kw++) {
                    uint4 q0 = __ldg(wp + kw * 2), q1 = __ldg(wp + kw * 2 + 1);
                    w[kw][0] = q0.x; w[kw][1] = q0.y; w[kw][2] = q0.z; w[kw][3] = q0.w;
                    w[kw][4] = q1.x; w[kw][5] = q1.y; w[kw][6] = q1.z; w[kw][7] = q1.w;
                }
                const uint32_t* rbase = ab + ((ry + kh) * PDIM + xs) * 8;
#pragma unroll
                for (int i = 0; i < 14; i++) {
                    int p1 = 0, p2 = 0;
#pragma unroll
                    for (int kw = 0; kw < 3; kw++) {
                        const uint4 a0 = *(const uint4*)(rbase + (i + kw) * 8);
                        const uint4 a1 = *(const uint4*)(rbase + (i + kw) * 8 + 4);
                        const uint32_t x0 = a0.x ^ w[kw][0], x1 = a0.y ^ w[kw][1];
                        const uint32_t x2 = a0.z ^ w[kw][2], x3 = a0.w ^ w[kw][3];
                        const uint32_t x4 = a1.x ^ w[kw][4], x5 = a1.y ^ w[kw][5];
                        const uint32_t x6 = a1.z ^ w[kw][6], x7 = a1.w ^ w[kw][7];
                        const uint32_t sA = xor3(x0, x1, x2), cA = maj3(x0, x1, x2);
                        const uint32_t sB = xor3(x3, x4, x5), cB = maj3(x3, x4, x5);
                        const uint32_t sC = x6 ^ x7,          cC = x6 & x7;
                        const uint32_t S  = xor3(sA, sB, sC), C  = maj3(sA, sB, sC);
                        p1 += __popc(S);
                        p2 += __popc(cA) + __popc(cB) + __popc(cC) + __popc(C);
                    }
                    acc[i] += p1 + 2 * p2;
                }
                asm volatile("" ::: "memory");
            }

            int cedge = (half == 0) ? (corr[0] + corr[3] + corr[6])
                                    : (corr[2] + corr[5] + corr[8]);
            if (y == 0)  cedge -= (half == 0) ? corr[0] : corr[2];
            if (y == 27) cedge -= (half == 0) ? corr[6] : corr[8];

#pragma unroll
            for (int i = 0; i < 14; i++) {
                int cs = rowc;
                if (half == 0 && i == 0)  cs += cedge;
                if (half == 1 && i == 13) cs += cedge;
                stage[lane * 29 + xs + i] = av * (float)(2304 - 2 * acc[i] - cs);
            }
        }

        __syncwarp();
        // per-warp coalesced writeback (stage region is private to this warp)
        if (lane < HW) {
            float* outb = out + ((size_t)(b * COUT + og * 32) * HW + y) * HW;
#pragma unroll 4
            for (int oo = 0; oo < 32; oo++)
                outb[(size_t)oo * NPIX + lane] = stage[oo * 29 + lane];
        }
        __syncwarp();
    }
}

// ---------------------------------------------------------------------------
extern "C" void kernel_launch(void* const* d_in, const int* in_sizes, int n_in,
                              void* d_out, int out_size)
{
    const float* x  = (const float*)d_in[0];
    const float* M  = (const float*)d_in[1];
    const float* Z  = (const float*)d_in[2];
    const float* al = (const float*)d_in[3];
    const float* rv = (const float*)d_in[4];

    cudaFuncSetAttribute(conv_pop_kernel,
                         cudaFuncAttributeMaxDynamicSharedMemorySize, SM_TOTAL);

    prep_kernel<<<COUT + (Bc * PPIX + 255) / 256, 256>>>(M, Z, rv, x);
    conv_pop_kernel<<<Bc * 4, 256, SM_TOTAL>>>(al, (float*)d_out);
}

// round 15
// speedup vs baseline: 1.1680x; 1.1680x over previous
#include <cuda_runtime.h>
#include <stdint.h>

#define Bc    64
#define CIN   256
#define COUT  256
#define HW    28
#define NPIX  (HW*HW)            // 784
#define NW    (COUT*CIN*9)       // 589824
#define KK    8
#define PDIM  30
#define PPIX  (PDIM*PDIM)        // 900

// ---------------- device scratch ----------------
__device__ __align__(16) uint32_t g_w[COUT * 9 * 8];          // [o][t][cw] sign bits
__device__ int                    g_corr[COUT * 9];           // 256 - 2*popc(w[o][t])
__device__ __align__(16) uint32_t g_pabits[(size_t)Bc * PPIX * 8]; // padded bit image

__device__ __forceinline__ uint32_t xor3(uint32_t a, uint32_t b, uint32_t c) {
    uint32_t r;
    asm("lop3.b32 %0, %1, %2, %3, 0x96;" : "=r"(r) : "r"(a), "r"(b), "r"(c));
    return r;
}
__device__ __forceinline__ uint32_t maj3(uint32_t a, uint32_t b, uint32_t c) {
    uint32_t r;
    asm("lop3.b32 %0, %1, %2, %3, 0xE8;" : "=r"(r) : "r"(a), "r"(b), "r"(c));
    return r;
}

// ---------------------------------------------------------------------------
// Kernel 1: fused prep. Blocks [0,256): weights; [256,481): activations.
// ---------------------------------------------------------------------------
__global__ void prep_kernel(const float* __restrict__ M, const float* __restrict__ Z,
                            const float* __restrict__ rv, const float* __restrict__ x)
{
    __shared__ float swv[2304];
    __shared__ int   sP[9];

    if (blockIdx.x < COUT) {
        const int o    = blockIdx.x;
        const int c    = threadIdx.x;
        const int lane = c & 31;
        const int cw   = c >> 5;

        if (c < 9) sP[c] = 0;

        float rvl[KK];
#pragma unroll
        for (int k = 0; k < KK; k++) rvl[k] = __ldg(rv + k);

        float wv9[9];
        {
            const float* Mp = M + (size_t)o * 2304;
#pragma unroll
            for (int i = 0; i < 9; i++) wv9[i] = Mp[i * 256 + c];
#pragma unroll
            for (int k = 0; k < KK; k++) {
                const float* zp = Z + (size_t)k * NW + (size_t)o * 2304;
#pragma unroll
                for (int i = 0; i < 9; i++) wv9[i] += rvl[k] * zp[i * 256 + c];
            }
        }
#pragma unroll
        for (int i = 0; i < 9; i++) swv[i * 256 + c] = wv9[i];
        __syncthreads();

#pragma unroll
        for (int j = 0; j < 9; j++) {
            unsigned bit  = __float_as_uint(swv[c * 9 + j]) >> 31;
            unsigned mask = __ballot_sync(0xffffffffu, bit);
            if (lane == 0) {
                g_w[(o * 9 + j) * 8 + cw] = mask;
                atomicAdd(&sP[j], __popc(mask));
            }
        }
        __syncthreads();
        if (c < 9) g_corr[o * 9 + c] = 256 - 2 * sP[c];
        return;
    }

    const int gid = (blockIdx.x - COUT) * 256 + threadIdx.x;
    if (gid >= Bc * PPIX) return;
    const int b  = gid / PPIX;
    const int pp = gid - b * PPIX;
    const int py = pp / PDIM;
    const int px = pp - py * PDIM;

    uint4* dst = (uint4*)(g_pabits + ((size_t)b * PPIX + pp) * 8);

    if (py == 0 || py == PDIM - 1 || px == 0 || px == PDIM - 1) {
        uint4 z = make_uint4(0, 0, 0, 0);
        dst[0] = z; dst[1] = z;
        return;
    }
    const float* xp = x + (size_t)b * CIN * NPIX + (py - 1) * HW + (px - 1);
    uint32_t w[8];
#pragma unroll
    for (int cw = 0; cw < 8; cw++) {
        uint32_t m = 0;
#pragma unroll
        for (int j = 0; j < 32; j++) {
            uint32_t s = __float_as_uint(xp[(size_t)(cw * 32 + j) * NPIX]) >> 31;
            m |= s << j;
        }
        w[cw] = m;
    }
    dst[0] = make_uint4(w[0], w[1], w[2], w[3]);
    dst[1] = make_uint4(w[4], w[5], w[6], w[7]);
}

// ---------------------------------------------------------------------------
// Kernel 2: CSA XNOR conv. 256 thr (8 warps = 8 og), 4-row bands, kh-outer
// weight streaming, two 14-col half-passes per row. 3 CTAs/SM -> 24 warps.
// grid <<<448, 256, 35456>>>
// ---------------------------------------------------------------------------
#define SM_ABITS 0                      // 6 rows x 30 px x 32B = 5760
#define SM_STAGE 5760                   // 8 og x 32 x 29 floats = 29696
#define SM_TOTAL (5760 + 29696)

__global__ void __launch_bounds__(256, 3)
conv_pop_kernel(const float* __restrict__ alpha, float* __restrict__ out)
{
    extern __shared__ __align__(16) uint8_t smem[];

    const int tid  = threadIdx.x;
    const int og   = tid >> 5;
    const int lane = tid & 31;

    const int b    = blockIdx.x / 7;
    const int band = blockIdx.x - b * 7;
    const int r0   = band * 4;

    // cooperative load: padded rows r0..r0+5 (360 uint4, contiguous)
    {
        const uint4* src = (const uint4*)(g_pabits + ((size_t)b * PPIX + r0 * PDIM) * 8);
        uint4* d4 = (uint4*)(smem + SM_ABITS);
        d4[tid] = src[tid];
        if (tid < 104) d4[tid + 256] = src[tid + 256];
    }

    const int o = og * 32 + lane;
    int corr[9];
#pragma unroll
    for (int t = 0; t < 9; t++) corr[t] = __ldg(g_corr + o * 9 + t);
    const float av = __ldg(alpha + o);
    const uint4* wbase = (const uint4*)(g_w + o * 72);

    __syncthreads();

    const uint32_t* ab = (const uint32_t*)(smem + SM_ABITS);
    float* stage = (float*)(smem + SM_STAGE) + og * (32 * 29);

#pragma unroll 1
    for (int ry = 0; ry < 4; ry++) {
        const int y = r0 + ry;

        const int rowc = (y == 0)  ? (corr[0] + corr[1] + corr[2])
                       : (y == 27) ? (corr[6] + corr[7] + corr[8]) : 0;

#pragma unroll 1
        for (int half = 0; half < 2; half++) {
            const int xs = half * 14;

            int acc[14];
#pragma unroll
            for (int i = 0; i < 14; i++) acc[i] = 0;

#pragma unroll 1
            for (int kh = 0; kh < 3; kh++) {
                const uint4* wp = wbase + kh * 6;
                uint32_t w[3][8];
#pragma unroll
                for (int kw = 0; kw < 3; kw++) {
                    uint4 q0 = __ldg(wp + kw * 2), q1 = __ldg(wp + kw * 2 + 1);
                    w[kw][0] = q0.x; w[kw][1] = q0.y; w[kw][2] = q0.z; w[kw][3] = q0.w;
                    w[kw][4] = q1.x; w[kw][5] = q1.y; w[kw][6] = q1.z; w[kw][7] = q1.w;
                }
                const uint32_t* rbase = ab + ((ry + kh) * PDIM + xs) * 8;
#pragma unroll
                for (int i = 0; i < 14; i++) {
                    int p1 = 0, p2 = 0;
#pragma unroll
                    for (int kw = 0; kw < 3; kw++) {
                        const uint4 a0 = *(const uint4*)(rbase + (i + kw) * 8);
                        const uint4 a1 = *(const uint4*)(rbase + (i + kw) * 8 + 4);
                        const uint32_t x0 = a0.x ^ w[kw][0], x1 = a0.y ^ w[kw][1];
                        const uint32_t x2 = a0.z ^ w[kw][2], x3 = a0.w ^ w[kw][3];
                        const uint32_t x4 = a1.x ^ w[kw][4], x5 = a1.y ^ w[kw][5];
                        const uint32_t x6 = a1.z ^ w[kw][6], x7 = a1.w ^ w[kw][7];
                        const uint32_t sA = xor3(x0, x1, x2), cA = maj3(x0, x1, x2);
                        const uint32_t sB = xor3(x3, x4, x5), cB = maj3(x3, x4, x5);
                        const uint32_t sC = x6 ^ x7,          cC = x6 & x7;
                        const uint32_t S  = xor3(sA, sB, sC), C  = maj3(sA, sB, sC);
                        p1 += __popc(S);
                        p2 += __popc(cA) + __popc(cB) + __popc(cC) + __popc(C);
                    }
                    acc[i] += p1 + 2 * p2;
                }
                asm volatile("" ::: "memory");
            }

            int cedge = (half == 0) ? (corr[0] + corr[3] + corr[6])
                                    : (corr[2] + corr[5] + corr[8]);
            if (y == 0)  cedge -= (half == 0) ? corr[0] : corr[2];
            if (y == 27) cedge -= (half == 0) ? corr[6] : corr[8];

#pragma unroll
            for (int i = 0; i < 14; i++) {
                int cs = rowc;
                if (half == 0 && i == 0)  cs += cedge;
                if (half == 1 && i == 13) cs += cedge;
                stage[lane * 29 + xs + i] = av * (float)(2304 - 2 * acc[i] - cs);
            }
        }

        __syncwarp();
        // per-warp coalesced writeback (stage region is private to this warp)
        if (lane < HW) {
            float* outb = out + ((size_t)(b * COUT + og * 32) * HW + y) * HW;
#pragma unroll 4
            for (int oo = 0; oo < 32; oo++)
                outb[(size_t)oo * NPIX + lane] = stage[oo * 29 + lane];
        }
        __syncwarp();
    }
}

// ---------------------------------------------------------------------------
extern "C" void kernel_launch(void* const* d_in, const int* in_sizes, int n_in,
                              void* d_out, int out_size)
{
    const float* x  = (const float*)d_in[0];
    const float* M  = (const float*)d_in[1];
    const float* Z  = (const float*)d_in[2];
    const float* al = (const float*)d_in[3];
    const float* rv = (const float*)d_in[4];

    cudaFuncSetAttribute(conv_pop_kernel,
                         cudaFuncAttributeMaxDynamicSharedMemorySize, SM_TOTAL);

    prep_kernel<<<COUT + (Bc * PPIX + 255) / 256, 256>>>(M, Z, rv, x);
    conv_pop_kernel<<<Bc * 7, 256, SM_TOTAL>>>(al, (float*)d_out);
}

// round 16
// speedup vs baseline: 1.2058x; 1.0324x over previous
#include <cuda_runtime.h>
#include <stdint.h>

#define Bc    64
#define CIN   256
#define COUT  256
#define HW    28
#define NPIX  (HW*HW)            // 784
#define NW    (COUT*CIN*9)       // 589824
#define KK    8
#define PDIM  30
#define PPIX  (PDIM*PDIM)        // 900

// ---------------- device scratch ----------------
__device__ __align__(16) uint32_t g_w[COUT * 9 * 8];          // [o][t][cw] sign bits
__device__ int                    g_corr[COUT * 9];           // 256 - 2*popc(w[o][t])
__device__ __align__(16) uint32_t g_pabits[(size_t)Bc * PPIX * 8]; // padded bit image

__device__ __forceinline__ uint32_t xor3(uint32_t a, uint32_t b, uint32_t c) {
    uint32_t r;
    asm("lop3.b32 %0, %1, %2, %3, 0x96;" : "=r"(r) : "r"(a), "r"(b), "r"(c));
    return r;
}
__device__ __forceinline__ uint32_t maj3(uint32_t a, uint32_t b, uint32_t c) {
    uint32_t r;
    asm("lop3.b32 %0, %1, %2, %3, 0xE8;" : "=r"(r) : "r"(a), "r"(b), "r"(c));
    return r;
}

// ---------------------------------------------------------------------------
// Kernel 1: fused prep. Blocks [0,256): weights; [256,1156): activations
// (4 threads per padded pixel -> 4x the latency-hiding of R15's version).
// ---------------------------------------------------------------------------
__global__ void prep_kernel(const float* __restrict__ M, const float* __restrict__ Z,
                            const float* __restrict__ rv, const float* __restrict__ x)
{
    __shared__ float swv[2304];
    __shared__ int   sP[9];

    if (blockIdx.x < COUT) {
        const int o    = blockIdx.x;
        const int c    = threadIdx.x;
        const int lane = c & 31;
        const int cw   = c >> 5;

        if (c < 9) sP[c] = 0;

        float rvl[KK];
#pragma unroll
        for (int k = 0; k < KK; k++) rvl[k] = __ldg(rv + k);

        float wv9[9];
        {
            const float* Mp = M + (size_t)o * 2304;
#pragma unroll
            for (int i = 0; i < 9; i++) wv9[i] = Mp[i * 256 + c];
#pragma unroll
            for (int k = 0; k < KK; k++) {
                const float* zp = Z + (size_t)k * NW + (size_t)o * 2304;
#pragma unroll
                for (int i = 0; i < 9; i++) wv9[i] += rvl[k] * zp[i * 256 + c];
            }
        }
#pragma unroll
        for (int i = 0; i < 9; i++) swv[i * 256 + c] = wv9[i];
        __syncthreads();

#pragma unroll
        for (int j = 0; j < 9; j++) {
            unsigned bit  = __float_as_uint(swv[c * 9 + j]) >> 31;
            unsigned mask = __ballot_sync(0xffffffffu, bit);
            if (lane == 0) {
                g_w[(o * 9 + j) * 8 + cw] = mask;
                atomicAdd(&sP[j], __popc(mask));
            }
        }
        __syncthreads();
        if (c < 9) g_corr[o * 9 + c] = 256 - 2 * sP[c];
        return;
    }

    // activations: 4 threads per (b, pp); thread packs 2 channel words (64 ch)
    const int gid = (blockIdx.x - COUT) * 256 + threadIdx.x;   // < 230400
    const int tq  = gid & 3;
    const int pix = gid >> 2;
    const int b   = pix / PPIX;
    const int pp  = pix - b * PPIX;
    const int py  = pp / PDIM;
    const int px  = pp - py * PDIM;

    uint2* dst = (uint2*)(g_pabits + ((size_t)b * PPIX + pp) * 8 + tq * 2);

    if (py == 0 || py == PDIM - 1 || px == 0 || px == PDIM - 1) {
        *dst = make_uint2(0, 0);
        return;
    }
    const float* xp = x + (size_t)b * CIN * NPIX + (size_t)(tq * 64) * NPIX
                        + (py - 1) * HW + (px - 1);
    uint32_t w0 = 0, w1 = 0;
#pragma unroll
    for (int j = 0; j < 32; j++) {
        w0 |= (__float_as_uint(xp[(size_t)j * NPIX]) >> 31) << j;
        w1 |= (__float_as_uint(xp[(size_t)(32 + j) * NPIX]) >> 31) << j;
    }
    *dst = make_uint2(w0, w1);
}

// ---------------------------------------------------------------------------
// Kernel 2: CSA XNOR conv with 2-level carry compression (4 popc/tap).
// 256 thr (8 warps = 8 og), 4-row bands, kh-streamed weights,
// two 14-col half-passes per row. 3 CTAs/SM. grid <<<448, 256, 35456>>>
// ---------------------------------------------------------------------------
#define SM_ABITS 0                      // 6 rows x 30 px x 32B = 5760
#define SM_STAGE 5760                   // 8 og x 32 x 29 floats = 29696
#define SM_TOTAL (5760 + 29696)

__global__ void __launch_bounds__(256, 3)
conv_pop_kernel(const float* __restrict__ alpha, float* __restrict__ out)
{
    extern __shared__ __align__(16) uint8_t smem[];

    const int tid  = threadIdx.x;
    const int og   = tid >> 5;
    const int lane = tid & 31;

    const int b    = blockIdx.x / 7;
    const int band = blockIdx.x - b * 7;
    const int r0   = band * 4;

    // cooperative load: padded rows r0..r0+5 (360 uint4, contiguous)
    {
        const uint4* src = (const uint4*)(g_pabits + ((size_t)b * PPIX + r0 * PDIM) * 8);
        uint4* d4 = (uint4*)(smem + SM_ABITS);
        d4[tid] = src[tid];
        if (tid < 104) d4[tid + 256] = src[tid + 256];
    }

    const int o = og * 32 + lane;
    int corr[9];
#pragma unroll
    for (int t = 0; t < 9; t++) corr[t] = __ldg(g_corr + o * 9 + t);
    const float av = __ldg(alpha + o);
    const uint4* wbase = (const uint4*)(g_w + o * 72);

    __syncthreads();

    const uint32_t* ab = (const uint32_t*)(smem + SM_ABITS);
    float* stage = (float*)(smem + SM_STAGE) + og * (32 * 29);

#pragma unroll 1
    for (int ry = 0; ry < 4; ry++) {
        const int y = r0 + ry;

        const int rowc = (y == 0)  ? (corr[0] + corr[1] + corr[2])
                       : (y == 27) ? (corr[6] + corr[7] + corr[8]) : 0;

#pragma unroll 1
        for (int half = 0; half < 2; half++) {
            const int xs = half * 14;

            int acc[14];
#pragma unroll
            for (int i = 0; i < 14; i++) acc[i] = 0;

#pragma unroll 1
            for (int kh = 0; kh < 3; kh++) {
                const uint4* wp = wbase + kh * 6;
                uint32_t w[3][8];
#pragma unroll
                for (int kw = 0; kw < 3; kw++) {
                    uint4 q0 = __ldg(wp + kw * 2), q1 = __ldg(wp + kw * 2 + 1);
                    w[kw][0] = q0.x; w[kw][1] = q0.y; w[kw][2] = q0.z; w[kw][3] = q0.w;
                    w[kw][4] = q1.x; w[kw][5] = q1.y; w[kw][6] = q1.z; w[kw][7] = q1.w;
                }
                const uint32_t* rbase = ab + ((ry + kh) * PDIM + xs) * 8;
#pragma unroll
                for (int i = 0; i < 14; i++) {
                    int p1 = 0, p2 = 0, p4 = 0;
#pragma unroll
                    for (int kw = 0; kw < 3; kw++) {
                        const uint4 a0 = *(const uint4*)(rbase + (i + kw) * 8);
                        const uint4 a1 = *(const uint4*)(rbase + (i + kw) * 8 + 4);
                        const uint32_t x0 = a0.x ^ w[kw][0], x1 = a0.y ^ w[kw][1];
                        const uint32_t x2 = a0.z ^ w[kw][2], x3 = a0.w ^ w[kw][3];
                        const uint32_t x4 = a1.x ^ w[kw][4], x5 = a1.y ^ w[kw][5];
                        const uint32_t x6 = a1.z ^ w[kw][6], x7 = a1.w ^ w[kw][7];
                        const uint32_t sA = xor3(x0, x1, x2), cA = maj3(x0, x1, x2);
                        const uint32_t sB = xor3(x3, x4, x5), cB = maj3(x3, x4, x5);
                        const uint32_t sC = x6 ^ x7,          cC = x6 & x7;
                        const uint32_t S  = xor3(sA, sB, sC), C  = maj3(sA, sB, sC);
                        const uint32_t s2 = xor3(cA, cB, cC), c4 = maj3(cA, cB, cC);
                        p1 += __popc(S);
                        p2 += __popc(C) + __popc(s2);
                        p4 += __popc(c4);
                    }
                    acc[i] += p1 + 2 * p2 + 4 * p4;
                }
                asm volatile("" ::: "memory");
            }

            int cedge = (half == 0) ? (corr[0] + corr[3] + corr[6])
                                    : (corr[2] + corr[5] + corr[8]);
            if (y == 0)  cedge -= (half == 0) ? corr[0] : corr[2];
            if (y == 27) cedge -= (half == 0) ? corr[6] : corr[8];

#pragma unroll
            for (int i = 0; i < 14; i++) {
                int cs = rowc;
                if (half == 0 && i == 0)  cs += cedge;
                if (half == 1 && i == 13) cs += cedge;
                stage[lane * 29 + xs + i] = av * (float)(2304 - 2 * acc[i] - cs);
            }
        }

        __syncwarp();
        // per-warp coalesced writeback (stage region is private to this warp)
        if (lane < HW) {
            float* outb = out + ((size_t)(b * COUT + og * 32) * HW + y) * HW;
#pragma unroll 4
            for (int oo = 0; oo < 32; oo++)
                outb[(size_t)oo * NPIX + lane] = stage[oo * 29 + lane];
        }
        __syncwarp();
    }
}

// ---------------------------------------------------------------------------
extern "C" void kernel_launch(void* const* d_in, const int* in_sizes, int n_in,
                              void* d_out, int out_size)
{
    const float* x  = (const float*)d_in[0];
    const float* M  = (const float*)d_in[1];
    const float* Z  = (const float*)d_in[2];
    const float* al = (const float*)d_in[3];
    const float* rv = (const float*)d_in[4];

    cudaFuncSetAttribute(conv_pop_kernel,
                         cudaFuncAttributeMaxDynamicSharedMemorySize, SM_TOTAL);

    prep_kernel<<<COUT + (Bc * PPIX * 4 + 255) / 256, 256>>>(M, Z, rv, x);
    conv_pop_kernel<<<Bc * 7, 256, SM_TOTAL>>>(al, (float*)d_out);
}